// round 4
// baseline (speedup 1.0000x reference)
#include <cuda_runtime.h>
#include <cstdint>
#include <cstddef>

// Problem constants
#define T_STEPS   101
#define B_SZ      16384
#define IN_DIM    40
#define HID       300
#define NPAD      320
#define OUT_DIM   12

#define WARPS_PER_BLK   4
#define THREADS_PER_BLK 128
#define ROWS_PER_WARP   4
#define ROWS_PER_BLK    (WARPS_PER_BLK * ROWS_PER_WARP)   // 16
#define NUM_BLKS        (B_SZ / ROWS_PER_BLK)             // 1024
#define AL_STRIDE       304

// Transposed, padded recurrent/ff weights (global, L2-resident: 384KB each)
__device__ float g_WhT[HID * NPAD];   // g_WhT[k*NPAD + i] = Wh[i*HID + k]
__device__ float g_W2T[HID * NPAD];

__global__ void prep_kernel(const float* __restrict__ Wh,
                            const float* __restrict__ W2) {
    int idx = blockIdx.x * blockDim.x + threadIdx.x;
    const int total = HID * NPAD;
    if (idx < total) {
        int k = idx / NPAD;
        int i = idx % NPAD;
        float wh = 0.0f, w2 = 0.0f;
        if (i < HID) {
            wh = Wh[i * HID + k];
            w2 = W2[i * HID + k];
        }
        g_WhT[idx] = wh;
        g_W2T[idx] = w2;
    }
}

// ---- packed f32x2 helpers (IEEE fp32 per lane; ptxas won't auto-fuse) ----
__device__ __forceinline__ unsigned long long pk2(float lo, float hi) {
    unsigned long long r;
    asm("mov.b64 %0, {%1, %2};" : "=l"(r) : "f"(lo), "f"(hi));
    return r;
}
__device__ __forceinline__ void upk2(unsigned long long v, float& lo, float& hi) {
    asm("mov.b64 {%0, %1}, %2;" : "=f"(lo), "=f"(hi) : "l"(v));
}
__device__ __forceinline__ void ffma2(unsigned long long& acc,
                                      unsigned long long a, unsigned long long b) {
    asm("fma.rn.f32x2 %0, %1, %2, %0;" : "+l"(acc) : "l"(a), "l"(b));
}
__device__ __forceinline__ void fadd2(unsigned long long& acc, unsigned long long a) {
    asm("add.rn.f32x2 %0, %0, %1;" : "+l"(acc) : "l"(a));
}
__device__ __forceinline__ unsigned long long fsub2(unsigned long long a,
                                                    unsigned long long b) {
    unsigned long long d;
    asm("sub.rn.f32x2 %0, %1, %2;" : "=l"(d) : "l"(a), "l"(b));
    return d;
}

// Neuron layout per lane L (pairs p=0..4):
//  p=0: (4L+0, 4L+1)   p=1: (4L+2, 4L+3)        [neurons 0..127]
//  p=2: (128+4L, +1)   p=3: (128+4L+2, +3)      [neurons 128..255]
//  p=4: (256+2L, 256+2L+1)                      [neurons 256..319]
__device__ __forceinline__ int neuron_of(int p, int e, int L) {
    return (p < 2) ? (4 * L + 2 * p + e)
         : (p < 4) ? (128 + 4 * L + 2 * (p - 2) + e)
                   : (256 + 2 * L + e);
}

__global__ void __launch_bounds__(THREADS_PER_BLK, 3)
snn_kernel(const float* __restrict__ x,
           const float* __restrict__ W1,
           const float* __restrict__ b1,
           const float* __restrict__ bh,
           const float* __restrict__ b2,
           const float* __restrict__ W3,
           const float* __restrict__ b3,
           float* __restrict__ out) {
    extern __shared__ char smem_raw[];
    float* W1Ts = (float*)smem_raw;                 // [IN_DIM][NPAD]  51200 B
    float* bsum = W1Ts + IN_DIM * NPAD;             // [NPAD] (b1+bh)
    float* b2s  = bsum + NPAD;                      // [NPAD]
    unsigned short* al = (unsigned short*)(b2s + NPAD);  // [16][AL_STRIDE]

    const int tid = threadIdx.x;

    for (int idx = tid; idx < IN_DIM * NPAD; idx += THREADS_PER_BLK) {
        int k = idx / NPAD;
        int h = idx % NPAD;
        W1Ts[idx] = (h < HID) ? W1[h * IN_DIM + k] : 0.0f;
    }
    for (int n = tid; n < NPAD; n += THREADS_PER_BLK) {
        bsum[n] = (n < HID) ? (b1[n] + bh[n]) : 0.0f;
        b2s[n]  = (n < HID) ? b2[n] : 0.0f;
    }
    __syncthreads();

    const int w = tid >> 5;
    const int L = tid & 31;
    const int row0 = (blockIdx.x * WARPS_PER_BLK + w) * ROWS_PER_WARP;
    unsigned short* lst[ROWS_PER_WARP];
#pragma unroll
    for (int r = 0; r < ROWS_PER_WARP; r++)
        lst[r] = al + (w * ROWS_PER_WARP + r) * AL_STRIDE;

    // LIF states as packed pairs
    unsigned long long v1[ROWS_PER_WARP][5], v2[ROWS_PER_WARP][5];
    unsigned long long cur[ROWS_PER_WARP][5];
    unsigned c2[ROWS_PER_WARP][3];
    int cnt[ROWS_PER_WARP];
#pragma unroll
    for (int r = 0; r < ROWS_PER_WARP; r++) {
#pragma unroll
        for (int p = 0; p < 5; p++) { v1[r][p] = 0ull; v2[r][p] = 0ull; }
        c2[r][0] = 0u; c2[r][1] = 0u; c2[r][2] = 0u;
        cnt[r] = 0;
    }
    const unsigned long long HALF2 = 0x3F0000003F000000ull;  // {0.5f, 0.5f}
    const unsigned lt_mask = (1u << L) - 1u;

    const float* xptr = x + (size_t)row0 * IN_DIM;
    const size_t xstep = (size_t)B_SZ * IN_DIM;

#pragma unroll 1
    for (int t = 0; t < T_STEPS; t++) {
        // ---- load x for 4 rows (IN_DIM = 32 + 8) ----
        float xa[ROWS_PER_WARP], xb[ROWS_PER_WARP];
#pragma unroll
        for (int r = 0; r < ROWS_PER_WARP; r++) {
            xa[r] = xptr[r * IN_DIM + L];
            xb[r] = (L < 8) ? xptr[r * IN_DIM + 32 + L] : 0.0f;
        }
        xptr += xstep;

        // ---- cur = bias (packed vector loads) ----
        {
            ulonglong2 bA = *(const ulonglong2*)(bsum + 4 * L);
            ulonglong2 bB = *(const ulonglong2*)(bsum + 128 + 4 * L);
            unsigned long long bC = *(const unsigned long long*)(bsum + 256 + 2 * L);
#pragma unroll
            for (int r = 0; r < ROWS_PER_WARP; r++) {
                cur[r][0] = bA.x; cur[r][1] = bA.y;
                cur[r][2] = bB.x; cur[r][3] = bB.y;
                cur[r][4] = bC;
            }
        }

        // ---- dense x @ W1^T (packed FFMA2, vector LDS) ----
#pragma unroll 4
        for (int k = 0; k < 32; k++) {
            const float* wr = W1Ts + k * NPAD;
            ulonglong2 wA = *(const ulonglong2*)(wr + 4 * L);
            ulonglong2 wB = *(const ulonglong2*)(wr + 128 + 4 * L);
            unsigned long long wC = *(const unsigned long long*)(wr + 256 + 2 * L);
#pragma unroll
            for (int r = 0; r < ROWS_PER_WARP; r++) {
                float xv = __shfl_sync(0xffffffffu, xa[r], k);
                unsigned long long xp = pk2(xv, xv);
                ffma2(cur[r][0], xp, wA.x);
                ffma2(cur[r][1], xp, wA.y);
                ffma2(cur[r][2], xp, wB.x);
                ffma2(cur[r][3], xp, wB.y);
                ffma2(cur[r][4], xp, wC);
            }
        }
#pragma unroll
        for (int k = 0; k < 8; k++) {
            const float* wr = W1Ts + (32 + k) * NPAD;
            ulonglong2 wA = *(const ulonglong2*)(wr + 4 * L);
            ulonglong2 wB = *(const ulonglong2*)(wr + 128 + 4 * L);
            unsigned long long wC = *(const unsigned long long*)(wr + 256 + 2 * L);
#pragma unroll
            for (int r = 0; r < ROWS_PER_WARP; r++) {
                float xv = __shfl_sync(0xffffffffu, xb[r], k);
                unsigned long long xp = pk2(xv, xv);
                ffma2(cur[r][0], xp, wA.x);
                ffma2(cur[r][1], xp, wA.y);
                ffma2(cur[r][2], xp, wB.x);
                ffma2(cur[r][3], xp, wB.y);
                ffma2(cur[r][4], xp, wC);
            }
        }

        // ---- sparse recurrent gathers (prev-step lists) ----
#pragma unroll
        for (int r = 0; r < ROWS_PER_WARP; r++) {
            const unsigned short* lr = lst[r];
            int cn = cnt[r];
            int i = 0;
            for (; i + 2 <= cn; i += 2) {
                const float* w0 = g_WhT + (int)lr[i] * NPAD;
                const float* w1g = g_WhT + (int)lr[i + 1] * NPAD;
                ulonglong2 a0 = *(const ulonglong2*)(w0 + 4 * L);
                ulonglong2 b0 = *(const ulonglong2*)(w0 + 128 + 4 * L);
                unsigned long long c0 = *(const unsigned long long*)(w0 + 256 + 2 * L);
                ulonglong2 a1 = *(const ulonglong2*)(w1g + 4 * L);
                ulonglong2 b1v = *(const ulonglong2*)(w1g + 128 + 4 * L);
                unsigned long long c1 = *(const unsigned long long*)(w1g + 256 + 2 * L);
                fadd2(cur[r][0], a0.x); fadd2(cur[r][1], a0.y);
                fadd2(cur[r][2], b0.x); fadd2(cur[r][3], b0.y);
                fadd2(cur[r][4], c0);
                fadd2(cur[r][0], a1.x); fadd2(cur[r][1], a1.y);
                fadd2(cur[r][2], b1v.x); fadd2(cur[r][3], b1v.y);
                fadd2(cur[r][4], c1);
            }
            if (i < cn) {
                const float* w0 = g_WhT + (int)lr[i] * NPAD;
                ulonglong2 a0 = *(const ulonglong2*)(w0 + 4 * L);
                ulonglong2 b0 = *(const ulonglong2*)(w0 + 128 + 4 * L);
                unsigned long long c0 = *(const unsigned long long*)(w0 + 256 + 2 * L);
                fadd2(cur[r][0], a0.x); fadd2(cur[r][1], a0.y);
                fadd2(cur[r][2], b0.x); fadd2(cur[r][3], b0.y);
                fadd2(cur[r][4], c0);
            }
        }
        __syncwarp();

        // ---- LIF 1 + rebuild spike lists ----
#pragma unroll
        for (int r = 0; r < ROWS_PER_WARP; r++) {
            int nc = 0;
#pragma unroll
            for (int p = 0; p < 5; p++) {
                unsigned long long d = fsub2(cur[r][p], v1[r][p]);
                unsigned long long vn = v1[r][p];
                ffma2(vn, d, HALF2);          // v + (cur - v)*0.5
                float lo, hi;
                upk2(vn, lo, hi);
                bool s0 = (lo >= 1.0f), s1 = (hi >= 1.0f);
                v1[r][p] = pk2(s0 ? 0.0f : lo, s1 ? 0.0f : hi);
                int nb = neuron_of(p, 0, L);
                unsigned m0 = __ballot_sync(0xffffffffu, s0);
                if (s0) lst[r][nc + __popc(m0 & lt_mask)] = (unsigned short)nb;
                nc += __popc(m0);
                unsigned m1 = __ballot_sync(0xffffffffu, s1);
                if (s1) lst[r][nc + __popc(m1 & lt_mask)] = (unsigned short)(nb + 1);
                nc += __popc(m1);
            }
            cnt[r] = nc;
        }
        __syncwarp();

        // ---- layer 2: bias + gather W2^T with new lists ----
        {
            ulonglong2 bA = *(const ulonglong2*)(b2s + 4 * L);
            ulonglong2 bB = *(const ulonglong2*)(b2s + 128 + 4 * L);
            unsigned long long bC = *(const unsigned long long*)(b2s + 256 + 2 * L);
#pragma unroll
            for (int r = 0; r < ROWS_PER_WARP; r++) {
                cur[r][0] = bA.x; cur[r][1] = bA.y;
                cur[r][2] = bB.x; cur[r][3] = bB.y;
                cur[r][4] = bC;
            }
        }
#pragma unroll
        for (int r = 0; r < ROWS_PER_WARP; r++) {
            const unsigned short* lr = lst[r];
            int cn = cnt[r];
            int i = 0;
            for (; i + 2 <= cn; i += 2) {
                const float* w0 = g_W2T + (int)lr[i] * NPAD;
                const float* w1g = g_W2T + (int)lr[i + 1] * NPAD;
                ulonglong2 a0 = *(const ulonglong2*)(w0 + 4 * L);
                ulonglong2 b0 = *(const ulonglong2*)(w0 + 128 + 4 * L);
                unsigned long long c0 = *(const unsigned long long*)(w0 + 256 + 2 * L);
                ulonglong2 a1 = *(const ulonglong2*)(w1g + 4 * L);
                ulonglong2 b1v = *(const ulonglong2*)(w1g + 128 + 4 * L);
                unsigned long long c1 = *(const unsigned long long*)(w1g + 256 + 2 * L);
                fadd2(cur[r][0], a0.x); fadd2(cur[r][1], a0.y);
                fadd2(cur[r][2], b0.x); fadd2(cur[r][3], b0.y);
                fadd2(cur[r][4], c0);
                fadd2(cur[r][0], a1.x); fadd2(cur[r][1], a1.y);
                fadd2(cur[r][2], b1v.x); fadd2(cur[r][3], b1v.y);
                fadd2(cur[r][4], c1);
            }
            if (i < cn) {
                const float* w0 = g_W2T + (int)lr[i] * NPAD;
                ulonglong2 a0 = *(const ulonglong2*)(w0 + 4 * L);
                ulonglong2 b0 = *(const ulonglong2*)(w0 + 128 + 4 * L);
                unsigned long long c0 = *(const unsigned long long*)(w0 + 256 + 2 * L);
                fadd2(cur[r][0], a0.x); fadd2(cur[r][1], a0.y);
                fadd2(cur[r][2], b0.x); fadd2(cur[r][3], b0.y);
                fadd2(cur[r][4], c0);
            }
        }

        // ---- LIF 2: packed update + 8-bit spike counters ----
#pragma unroll
        for (int r = 0; r < ROWS_PER_WARP; r++) {
#pragma unroll
            for (int p = 0; p < 5; p++) {
                unsigned long long d = fsub2(cur[r][p], v2[r][p]);
                unsigned long long vn = v2[r][p];
                ffma2(vn, d, HALF2);
                float lo, hi;
                upk2(vn, lo, hi);
                bool s0 = (lo >= 1.0f), s1 = (hi >= 1.0f);
                v2[r][p] = pk2(s0 ? 0.0f : lo, s1 ? 0.0f : hi);
                int s_lo = 2 * p, s_hi = 2 * p + 1;
                c2[r][s_lo >> 2] += s0 ? (1u << (8 * (s_lo & 3))) : 0u;
                c2[r][s_hi >> 2] += s1 ? (1u << (8 * (s_hi & 3))) : 0u;
            }
        }
    }

    // ---- epilogue: out[row] = counts @ W3^T + 101*b3 ----
#pragma unroll
    for (int r = 0; r < ROWS_PER_WARP; r++) {
        float acc[OUT_DIM];
#pragma unroll
        for (int o = 0; o < OUT_DIM; o++) acc[o] = 0.0f;
#pragma unroll
        for (int s = 0; s < 10; s++) {
            int p = s >> 1, e = s & 1;
            int n = neuron_of(p, e, L);
            float c = (float)((c2[r][s >> 2] >> (8 * (s & 3))) & 255u);
            if (n < HID && c != 0.0f) {
#pragma unroll
                for (int o = 0; o < OUT_DIM; o++)
                    acc[o] = fmaf(c, W3[o * HID + n], acc[o]);
            }
        }
#pragma unroll
        for (int o = 0; o < OUT_DIM; o++) {
            float sv = acc[o];
            sv += __shfl_xor_sync(0xffffffffu, sv, 16);
            sv += __shfl_xor_sync(0xffffffffu, sv, 8);
            sv += __shfl_xor_sync(0xffffffffu, sv, 4);
            sv += __shfl_xor_sync(0xffffffffu, sv, 2);
            sv += __shfl_xor_sync(0xffffffffu, sv, 1);
            if (L == 0) out[(row0 + r) * OUT_DIM + o] = sv + 101.0f * b3[o];
        }
    }
}

extern "C" void kernel_launch(void* const* d_in, const int* in_sizes, int n_in,
                              void* d_out, int out_size) {
    const float* x  = (const float*)d_in[0];
    const float* W1 = (const float*)d_in[1];
    const float* b1 = (const float*)d_in[2];
    const float* Wh = (const float*)d_in[3];
    const float* bh = (const float*)d_in[4];
    const float* W2 = (const float*)d_in[5];
    const float* b2 = (const float*)d_in[6];
    const float* W3 = (const float*)d_in[7];
    const float* b3 = (const float*)d_in[8];
    float* out = (float*)d_out;

    {
        int total = HID * NPAD;
        int threads = 256;
        int blocks = (total + threads - 1) / threads;
        prep_kernel<<<blocks, threads>>>(Wh, W2);
    }

    size_t smem = (size_t)IN_DIM * NPAD * 4     // W1Ts
                + NPAD * 4                       // bsum
                + NPAD * 4                       // b2s
                + (size_t)ROWS_PER_BLK * AL_STRIDE * 2;
    cudaFuncSetAttribute(snn_kernel, cudaFuncAttributeMaxDynamicSharedMemorySize,
                         (int)smem);
    snn_kernel<<<NUM_BLKS, THREADS_PER_BLK, smem>>>(x, W1, b1, bh, b2, W3, b3, out);
}

// round 5
// speedup vs baseline: 1.0050x; 1.0050x over previous
#include <cuda_runtime.h>
#include <cstdint>
#include <cstddef>

// Problem constants
#define T_STEPS   101
#define B_SZ      16384
#define IN_DIM    40
#define HID       300
#define HID_PAD   304        // rows 300..303 are zero (dummy gather target)
#define NPAD      320
#define OUT_DIM   12
#define DUMMY_IDX 300

#define WARPS_PER_BLK   4
#define THREADS_PER_BLK 128
#define ROWS_PER_WARP   4
#define ROWS_PER_BLK    (WARPS_PER_BLK * ROWS_PER_WARP)   // 16
#define NUM_BLKS        (B_SZ / ROWS_PER_BLK)             // 1024
#define AL_STRIDE       308   // 300 max spikes + 3 dummy pads (u16)

// Transposed, padded recurrent/ff weights (global, L2-resident: ~389KB each)
__device__ float g_WhT[HID_PAD * NPAD];   // g_WhT[k*NPAD + i] = Wh[i*HID + k]; rows>=300 zero
__device__ float g_W2T[HID_PAD * NPAD];

__global__ void prep_kernel(const float* __restrict__ Wh,
                            const float* __restrict__ W2) {
    int idx = blockIdx.x * blockDim.x + threadIdx.x;
    const int total = HID_PAD * NPAD;
    if (idx < total) {
        int k = idx / NPAD;
        int i = idx % NPAD;
        float wh = 0.0f, w2 = 0.0f;
        if (i < HID && k < HID) {
            wh = Wh[i * HID + k];
            w2 = W2[i * HID + k];
        }
        g_WhT[idx] = wh;
        g_W2T[idx] = w2;
    }
}

// ---- packed f32x2 helpers ----
__device__ __forceinline__ unsigned long long pk2(float lo, float hi) {
    unsigned long long r;
    asm("mov.b64 %0, {%1, %2};" : "=l"(r) : "f"(lo), "f"(hi));
    return r;
}
__device__ __forceinline__ void upk2(unsigned long long v, float& lo, float& hi) {
    asm("mov.b64 {%0, %1}, %2;" : "=f"(lo), "=f"(hi) : "l"(v));
}
__device__ __forceinline__ void ffma2(unsigned long long& acc,
                                      unsigned long long a, unsigned long long b) {
    asm("fma.rn.f32x2 %0, %1, %2, %0;" : "+l"(acc) : "l"(a), "l"(b));
}
__device__ __forceinline__ void fadd2(unsigned long long& acc, unsigned long long a) {
    asm("add.rn.f32x2 %0, %0, %1;" : "+l"(acc) : "l"(a));
}
__device__ __forceinline__ unsigned long long fsub2(unsigned long long a,
                                                    unsigned long long b) {
    unsigned long long d;
    asm("sub.rn.f32x2 %0, %1, %2;" : "=l"(d) : "l"(a), "l"(b));
    return d;
}

// Neuron layout per lane L (pairs p=0..4):
//  p=0: (4L+0, 4L+1)   p=1: (4L+2, 4L+3)        [neurons 0..127]
//  p=2: (128+4L, +1)   p=3: (128+4L+2, +3)      [neurons 128..255]
//  p=4: (256+2L, 256+2L+1)                      [neurons 256..319]
__device__ __forceinline__ int neuron_of(int p, int e, int L) {
    return (p < 2) ? (4 * L + 2 * p + e)
         : (p < 4) ? (128 + 4 * L + 2 * (p - 2) + e)
                   : (256 + 2 * L + e);
}

// gather-add two spike rows (may be zero dummy rows) into cur[5]
__device__ __forceinline__ void gather2(const float* __restrict__ g,
                                        const unsigned short* __restrict__ lr,
                                        int i, int L, unsigned long long* c) {
    const float* w0 = g + (int)lr[i] * NPAD;
    const float* w1 = g + (int)lr[i + 1] * NPAD;
    ulonglong2 a0 = *(const ulonglong2*)(w0 + 4 * L);
    ulonglong2 b0 = *(const ulonglong2*)(w0 + 128 + 4 * L);
    unsigned long long c0 = *(const unsigned long long*)(w0 + 256 + 2 * L);
    ulonglong2 a1 = *(const ulonglong2*)(w1 + 4 * L);
    ulonglong2 b1 = *(const ulonglong2*)(w1 + 128 + 4 * L);
    unsigned long long c1 = *(const unsigned long long*)(w1 + 256 + 2 * L);
    fadd2(c[0], a0.x); fadd2(c[1], a0.y);
    fadd2(c[2], b0.x); fadd2(c[3], b0.y);
    fadd2(c[4], c0);
    fadd2(c[0], a1.x); fadd2(c[1], a1.y);
    fadd2(c[2], b1.x); fadd2(c[3], b1.y);
    fadd2(c[4], c1);
}

__global__ void __launch_bounds__(THREADS_PER_BLK, 3)
snn_kernel(const float* __restrict__ x,
           const float* __restrict__ W1,
           const float* __restrict__ b1,
           const float* __restrict__ bh,
           const float* __restrict__ b2,
           const float* __restrict__ W3,
           const float* __restrict__ b3,
           float* __restrict__ out) {
    extern __shared__ char smem_raw[];
    float* W1Ts = (float*)smem_raw;                 // [IN_DIM][NPAD]  51200 B
    float* bsum = W1Ts + IN_DIM * NPAD;             // [NPAD] (b1+bh)
    float* b2s  = bsum + NPAD;                      // [NPAD]
    unsigned short* al = (unsigned short*)(b2s + NPAD);  // [16][AL_STRIDE]

    const int tid = threadIdx.x;

    for (int idx = tid; idx < IN_DIM * NPAD; idx += THREADS_PER_BLK) {
        int k = idx / NPAD;
        int h = idx % NPAD;
        W1Ts[idx] = (h < HID) ? W1[h * IN_DIM + k] : 0.0f;
    }
    for (int n = tid; n < NPAD; n += THREADS_PER_BLK) {
        bsum[n] = (n < HID) ? (b1[n] + bh[n]) : 0.0f;
        b2s[n]  = (n < HID) ? b2[n] : 0.0f;
    }
    __syncthreads();

    const int w = tid >> 5;
    const int L = tid & 31;
    const int row0 = (blockIdx.x * WARPS_PER_BLK + w) * ROWS_PER_WARP;
    unsigned short* lst[ROWS_PER_WARP];
#pragma unroll
    for (int r = 0; r < ROWS_PER_WARP; r++)
        lst[r] = al + (w * ROWS_PER_WARP + r) * AL_STRIDE;

    // LIF states as packed pairs
    unsigned long long v1[ROWS_PER_WARP][5], v2[ROWS_PER_WARP][5];
    unsigned long long cur[ROWS_PER_WARP][5];
    unsigned c2[ROWS_PER_WARP][3];
    int cnt[ROWS_PER_WARP];
#pragma unroll
    for (int r = 0; r < ROWS_PER_WARP; r++) {
#pragma unroll
        for (int p = 0; p < 5; p++) { v1[r][p] = 0ull; v2[r][p] = 0ull; }
        c2[r][0] = 0u; c2[r][1] = 0u; c2[r][2] = 0u;
        cnt[r] = 0;
    }
    const unsigned long long HALF2 = 0x3F0000003F000000ull;  // {0.5f, 0.5f}
    const unsigned lt_mask = (1u << L) - 1u;

    const float* xptr = x + (size_t)row0 * IN_DIM;
    const size_t xstep = (size_t)B_SZ * IN_DIM;

#pragma unroll 1
    for (int t = 0; t < T_STEPS; t++) {
        // ---- load x for 4 rows (IN_DIM = 32 + 8) ----
        float xa[ROWS_PER_WARP], xb[ROWS_PER_WARP];
#pragma unroll
        for (int r = 0; r < ROWS_PER_WARP; r++) {
            xa[r] = xptr[r * IN_DIM + L];
            xb[r] = (L < 8) ? xptr[r * IN_DIM + 32 + L] : 0.0f;
        }
        xptr += xstep;

        // ---- prefetch next step's x slab (640B, 5 lines) into L2 ----
        if (t + 1 < T_STEPS && L < 5) {
            const float* nx = xptr + L * 32;
            asm volatile("prefetch.global.L2 [%0];" :: "l"(nx));
        }

        // ---- cur = bias (packed vector loads) ----
        {
            ulonglong2 bA = *(const ulonglong2*)(bsum + 4 * L);
            ulonglong2 bB = *(const ulonglong2*)(bsum + 128 + 4 * L);
            unsigned long long bC = *(const unsigned long long*)(bsum + 256 + 2 * L);
#pragma unroll
            for (int r = 0; r < ROWS_PER_WARP; r++) {
                cur[r][0] = bA.x; cur[r][1] = bA.y;
                cur[r][2] = bB.x; cur[r][3] = bB.y;
                cur[r][4] = bC;
            }
        }

        // ---- dense x @ W1^T (packed FFMA2, vector LDS) ----
#pragma unroll 4
        for (int k = 0; k < 32; k++) {
            const float* wr = W1Ts + k * NPAD;
            ulonglong2 wA = *(const ulonglong2*)(wr + 4 * L);
            ulonglong2 wB = *(const ulonglong2*)(wr + 128 + 4 * L);
            unsigned long long wC = *(const unsigned long long*)(wr + 256 + 2 * L);
#pragma unroll
            for (int r = 0; r < ROWS_PER_WARP; r++) {
                float xv = __shfl_sync(0xffffffffu, xa[r], k);
                unsigned long long xp = pk2(xv, xv);
                ffma2(cur[r][0], xp, wA.x);
                ffma2(cur[r][1], xp, wA.y);
                ffma2(cur[r][2], xp, wB.x);
                ffma2(cur[r][3], xp, wB.y);
                ffma2(cur[r][4], xp, wC);
            }
        }
#pragma unroll
        for (int k = 0; k < 8; k++) {
            const float* wr = W1Ts + (32 + k) * NPAD;
            ulonglong2 wA = *(const ulonglong2*)(wr + 4 * L);
            ulonglong2 wB = *(const ulonglong2*)(wr + 128 + 4 * L);
            unsigned long long wC = *(const unsigned long long*)(wr + 256 + 2 * L);
#pragma unroll
            for (int r = 0; r < ROWS_PER_WARP; r++) {
                float xv = __shfl_sync(0xffffffffu, xb[r], k);
                unsigned long long xp = pk2(xv, xv);
                ffma2(cur[r][0], xp, wA.x);
                ffma2(cur[r][1], xp, wA.y);
                ffma2(cur[r][2], xp, wB.x);
                ffma2(cur[r][3], xp, wB.y);
                ffma2(cur[r][4], xp, wC);
            }
        }

        // ---- sparse recurrent gathers (prev-step lists, dummy-padded, unroll x4) ----
#pragma unroll
        for (int r = 0; r < ROWS_PER_WARP; r++) {
            const unsigned short* lr = lst[r];
            const int cn = cnt[r];
#pragma unroll 1
            for (int i = 0; i < cn; i += 4) {
                gather2(g_WhT, lr, i, L, cur[r]);
                gather2(g_WhT, lr, i + 2, L, cur[r]);
            }
        }
        __syncwarp();

        // ---- LIF 1 + rebuild spike lists (+3 dummy pads) ----
#pragma unroll
        for (int r = 0; r < ROWS_PER_WARP; r++) {
            int nc = 0;
#pragma unroll
            for (int p = 0; p < 5; p++) {
                unsigned long long d = fsub2(cur[r][p], v1[r][p]);
                unsigned long long vn = v1[r][p];
                ffma2(vn, d, HALF2);          // v + (cur - v)*0.5
                float lo, hi;
                upk2(vn, lo, hi);
                bool s0 = (lo >= 1.0f), s1 = (hi >= 1.0f);
                v1[r][p] = pk2(s0 ? 0.0f : lo, s1 ? 0.0f : hi);
                int nb = neuron_of(p, 0, L);
                unsigned m0 = __ballot_sync(0xffffffffu, s0);
                if (s0) lst[r][nc + __popc(m0 & lt_mask)] = (unsigned short)nb;
                nc += __popc(m0);
                unsigned m1 = __ballot_sync(0xffffffffu, s1);
                if (s1) lst[r][nc + __popc(m1 & lt_mask)] = (unsigned short)(nb + 1);
                nc += __popc(m1);
            }
            if (L < 3) lst[r][nc + L] = (unsigned short)DUMMY_IDX;  // pad for unroll-4
            cnt[r] = nc;
        }
        __syncwarp();

        // ---- layer 2: bias + gather W2^T with new lists ----
        {
            ulonglong2 bA = *(const ulonglong2*)(b2s + 4 * L);
            ulonglong2 bB = *(const ulonglong2*)(b2s + 128 + 4 * L);
            unsigned long long bC = *(const unsigned long long*)(b2s + 256 + 2 * L);
#pragma unroll
            for (int r = 0; r < ROWS_PER_WARP; r++) {
                cur[r][0] = bA.x; cur[r][1] = bA.y;
                cur[r][2] = bB.x; cur[r][3] = bB.y;
                cur[r][4] = bC;
            }
        }
#pragma unroll
        for (int r = 0; r < ROWS_PER_WARP; r++) {
            const unsigned short* lr = lst[r];
            const int cn = cnt[r];
#pragma unroll 1
            for (int i = 0; i < cn; i += 4) {
                gather2(g_W2T, lr, i, L, cur[r]);
                gather2(g_W2T, lr, i + 2, L, cur[r]);
            }
        }

        // ---- LIF 2: packed update + 8-bit spike counters ----
#pragma unroll
        for (int r = 0; r < ROWS_PER_WARP; r++) {
#pragma unroll
            for (int p = 0; p < 5; p++) {
                unsigned long long d = fsub2(cur[r][p], v2[r][p]);
                unsigned long long vn = v2[r][p];
                ffma2(vn, d, HALF2);
                float lo, hi;
                upk2(vn, lo, hi);
                bool s0 = (lo >= 1.0f), s1 = (hi >= 1.0f);
                v2[r][p] = pk2(s0 ? 0.0f : lo, s1 ? 0.0f : hi);
                int s_lo = 2 * p, s_hi = 2 * p + 1;
                c2[r][s_lo >> 2] += s0 ? (1u << (8 * (s_lo & 3))) : 0u;
                c2[r][s_hi >> 2] += s1 ? (1u << (8 * (s_hi & 3))) : 0u;
            }
        }
    }

    // ---- epilogue: out[row] = counts @ W3^T + 101*b3 ----
#pragma unroll
    for (int r = 0; r < ROWS_PER_WARP; r++) {
        float acc[OUT_DIM];
#pragma unroll
        for (int o = 0; o < OUT_DIM; o++) acc[o] = 0.0f;
#pragma unroll
        for (int s = 0; s < 10; s++) {
            int p = s >> 1, e = s & 1;
            int n = neuron_of(p, e, L);
            float c = (float)((c2[r][s >> 2] >> (8 * (s & 3))) & 255u);
            if (n < HID && c != 0.0f) {
#pragma unroll
                for (int o = 0; o < OUT_DIM; o++)
                    acc[o] = fmaf(c, W3[o * HID + n], acc[o]);
            }
        }
#pragma unroll
        for (int o = 0; o < OUT_DIM; o++) {
            float sv = acc[o];
            sv += __shfl_xor_sync(0xffffffffu, sv, 16);
            sv += __shfl_xor_sync(0xffffffffu, sv, 8);
            sv += __shfl_xor_sync(0xffffffffu, sv, 4);
            sv += __shfl_xor_sync(0xffffffffu, sv, 2);
            sv += __shfl_xor_sync(0xffffffffu, sv, 1);
            if (L == 0) out[(row0 + r) * OUT_DIM + o] = sv + 101.0f * b3[o];
        }
    }
}

extern "C" void kernel_launch(void* const* d_in, const int* in_sizes, int n_in,
                              void* d_out, int out_size) {
    const float* x  = (const float*)d_in[0];
    const float* W1 = (const float*)d_in[1];
    const float* b1 = (const float*)d_in[2];
    const float* Wh = (const float*)d_in[3];
    const float* bh = (const float*)d_in[4];
    const float* W2 = (const float*)d_in[5];
    const float* b2 = (const float*)d_in[6];
    const float* W3 = (const float*)d_in[7];
    const float* b3 = (const float*)d_in[8];
    float* out = (float*)d_out;

    {
        int total = HID_PAD * NPAD;
        int threads = 256;
        int blocks = (total + threads - 1) / threads;
        prep_kernel<<<blocks, threads>>>(Wh, W2);
    }

    size_t smem = (size_t)IN_DIM * NPAD * 4     // W1Ts
                + NPAD * 4                       // bsum
                + NPAD * 4                       // b2s
                + (size_t)ROWS_PER_BLK * AL_STRIDE * 2;
    cudaFuncSetAttribute(snn_kernel, cudaFuncAttributeMaxDynamicSharedMemorySize,
                         (int)smem);
    snn_kernel<<<NUM_BLKS, THREADS_PER_BLK, smem>>>(x, W1, b1, bh, b2, W3, b3, out);
}

// round 6
// speedup vs baseline: 1.1140x; 1.1084x over previous
#include <cuda_runtime.h>
#include <cstdint>
#include <cstddef>

// Problem constants
#define T_STEPS   101
#define B_SZ      16384
#define IN_DIM    40
#define HID       300
#define NPAD      320
#define OUT_DIM   12

#define WARPS_PER_BLK   8
#define THREADS_PER_BLK 256
#define ROWS_PER_WARP   2
#define ROWS_PER_BLK    (WARPS_PER_BLK * ROWS_PER_WARP)   // 16
#define NUM_BLKS        (B_SZ / ROWS_PER_BLK)             // 1024
#define AL_STRIDE       304

// Transposed, padded recurrent/ff weights (global, L2/L1-resident: 384KB each)
__device__ float g_WhT[HID * NPAD];   // g_WhT[k*NPAD + i] = Wh[i*HID + k]
__device__ float g_W2T[HID * NPAD];

__global__ void prep_kernel(const float* __restrict__ Wh,
                            const float* __restrict__ W2) {
    int idx = blockIdx.x * blockDim.x + threadIdx.x;
    const int total = HID * NPAD;
    if (idx < total) {
        int k = idx / NPAD;
        int i = idx % NPAD;
        float wh = 0.0f, w2 = 0.0f;
        if (i < HID) {
            wh = Wh[i * HID + k];
            w2 = W2[i * HID + k];
        }
        g_WhT[idx] = wh;
        g_W2T[idx] = w2;
    }
}

// ---- packed f32x2 helpers (IEEE fp32 per lane) ----
__device__ __forceinline__ unsigned long long pk2(float lo, float hi) {
    unsigned long long r;
    asm("mov.b64 %0, {%1, %2};" : "=l"(r) : "f"(lo), "f"(hi));
    return r;
}
__device__ __forceinline__ void upk2(unsigned long long v, float& lo, float& hi) {
    asm("mov.b64 {%0, %1}, %2;" : "=f"(lo), "=f"(hi) : "l"(v));
}
__device__ __forceinline__ void ffma2(unsigned long long& acc,
                                      unsigned long long a, unsigned long long b) {
    asm("fma.rn.f32x2 %0, %1, %2, %0;" : "+l"(acc) : "l"(a), "l"(b));
}
__device__ __forceinline__ void fadd2(unsigned long long& acc, unsigned long long a) {
    asm("add.rn.f32x2 %0, %0, %1;" : "+l"(acc) : "l"(a));
}
__device__ __forceinline__ unsigned long long fsub2(unsigned long long a,
                                                    unsigned long long b) {
    unsigned long long d;
    asm("sub.rn.f32x2 %0, %1, %2;" : "=l"(d) : "l"(a), "l"(b));
    return d;
}

// Neuron layout per lane L (pairs p=0..4):
//  p=0: (4L+0, 4L+1)   p=1: (4L+2, 4L+3)        [neurons 0..127]
//  p=2: (128+4L, +1)   p=3: (128+4L+2, +3)      [neurons 128..255]
//  p=4: (256+2L, 256+2L+1)                      [neurons 256..319]
__device__ __forceinline__ int neuron_of(int p, int e, int L) {
    return (p < 2) ? (4 * L + 2 * p + e)
         : (p < 4) ? (128 + 4 * L + 2 * (p - 2) + e)
                   : (256 + 2 * L + e);
}

// gather-add one spike row into cur[5] (vectorized)
__device__ __forceinline__ void gather1(const float* __restrict__ w0,
                                        int L, unsigned long long* c) {
    ulonglong2 a0 = *(const ulonglong2*)(w0 + 4 * L);
    ulonglong2 b0 = *(const ulonglong2*)(w0 + 128 + 4 * L);
    unsigned long long c0 = *(const unsigned long long*)(w0 + 256 + 2 * L);
    fadd2(c[0], a0.x); fadd2(c[1], a0.y);
    fadd2(c[2], b0.x); fadd2(c[3], b0.y);
    fadd2(c[4], c0);
}

__global__ void __launch_bounds__(THREADS_PER_BLK, 2)
snn_kernel(const float* __restrict__ x,
           const float* __restrict__ W1,
           const float* __restrict__ b1,
           const float* __restrict__ bh,
           const float* __restrict__ b2,
           const float* __restrict__ W3,
           const float* __restrict__ b3,
           float* __restrict__ out) {
    extern __shared__ char smem_raw[];
    float* W1Ts = (float*)smem_raw;                 // [IN_DIM][NPAD]  51200 B
    float* bsum = W1Ts + IN_DIM * NPAD;             // [NPAD] (b1+bh)
    float* b2s  = bsum + NPAD;                      // [NPAD]
    unsigned short* al = (unsigned short*)(b2s + NPAD);  // [16][AL_STRIDE]

    const int tid = threadIdx.x;

    for (int idx = tid; idx < IN_DIM * NPAD; idx += THREADS_PER_BLK) {
        int k = idx / NPAD;
        int h = idx % NPAD;
        W1Ts[idx] = (h < HID) ? W1[h * IN_DIM + k] : 0.0f;
    }
    for (int n = tid; n < NPAD; n += THREADS_PER_BLK) {
        bsum[n] = (n < HID) ? (b1[n] + bh[n]) : 0.0f;
        b2s[n]  = (n < HID) ? b2[n] : 0.0f;
    }
    __syncthreads();

    const int w = tid >> 5;
    const int L = tid & 31;
    const int row0 = (blockIdx.x * WARPS_PER_BLK + w) * ROWS_PER_WARP;
    unsigned short* lst[ROWS_PER_WARP];
#pragma unroll
    for (int r = 0; r < ROWS_PER_WARP; r++)
        lst[r] = al + (w * ROWS_PER_WARP + r) * AL_STRIDE;

    // LIF states as packed pairs
    unsigned long long v1[ROWS_PER_WARP][5], v2[ROWS_PER_WARP][5];
    unsigned long long cur[ROWS_PER_WARP][5];
    unsigned c2[ROWS_PER_WARP][3];
    int cnt[ROWS_PER_WARP];
#pragma unroll
    for (int r = 0; r < ROWS_PER_WARP; r++) {
#pragma unroll
        for (int p = 0; p < 5; p++) { v1[r][p] = 0ull; v2[r][p] = 0ull; }
        c2[r][0] = 0u; c2[r][1] = 0u; c2[r][2] = 0u;
        cnt[r] = 0;
    }
    const unsigned long long HALF2 = 0x3F0000003F000000ull;  // {0.5f, 0.5f}
    const unsigned lt_mask = (1u << L) - 1u;

    const float* xptr = x + (size_t)row0 * IN_DIM;
    const size_t xstep = (size_t)B_SZ * IN_DIM;

#pragma unroll 1
    for (int t = 0; t < T_STEPS; t++) {
        // ---- load x for 2 rows (IN_DIM = 32 + 8) ----
        float xa[ROWS_PER_WARP], xb[ROWS_PER_WARP];
#pragma unroll
        for (int r = 0; r < ROWS_PER_WARP; r++) {
            xa[r] = xptr[r * IN_DIM + L];
            xb[r] = (L < 8) ? xptr[r * IN_DIM + 32 + L] : 0.0f;
        }
        xptr += xstep;

        // ---- cur = bias (packed vector loads) ----
        {
            ulonglong2 bA = *(const ulonglong2*)(bsum + 4 * L);
            ulonglong2 bB = *(const ulonglong2*)(bsum + 128 + 4 * L);
            unsigned long long bC = *(const unsigned long long*)(bsum + 256 + 2 * L);
#pragma unroll
            for (int r = 0; r < ROWS_PER_WARP; r++) {
                cur[r][0] = bA.x; cur[r][1] = bA.y;
                cur[r][2] = bB.x; cur[r][3] = bB.y;
                cur[r][4] = bC;
            }
        }

        // ---- dense x @ W1^T (packed FFMA2, vector LDS) ----
#pragma unroll 4
        for (int k = 0; k < 32; k++) {
            const float* wr = W1Ts + k * NPAD;
            ulonglong2 wA = *(const ulonglong2*)(wr + 4 * L);
            ulonglong2 wB = *(const ulonglong2*)(wr + 128 + 4 * L);
            unsigned long long wC = *(const unsigned long long*)(wr + 256 + 2 * L);
#pragma unroll
            for (int r = 0; r < ROWS_PER_WARP; r++) {
                float xv = __shfl_sync(0xffffffffu, xa[r], k);
                unsigned long long xp = pk2(xv, xv);
                ffma2(cur[r][0], xp, wA.x);
                ffma2(cur[r][1], xp, wA.y);
                ffma2(cur[r][2], xp, wB.x);
                ffma2(cur[r][3], xp, wB.y);
                ffma2(cur[r][4], xp, wC);
            }
        }
#pragma unroll
        for (int k = 0; k < 8; k++) {
            const float* wr = W1Ts + (32 + k) * NPAD;
            ulonglong2 wA = *(const ulonglong2*)(wr + 4 * L);
            ulonglong2 wB = *(const ulonglong2*)(wr + 128 + 4 * L);
            unsigned long long wC = *(const unsigned long long*)(wr + 256 + 2 * L);
#pragma unroll
            for (int r = 0; r < ROWS_PER_WARP; r++) {
                float xv = __shfl_sync(0xffffffffu, xb[r], k);
                unsigned long long xp = pk2(xv, xv);
                ffma2(cur[r][0], xp, wA.x);
                ffma2(cur[r][1], xp, wA.y);
                ffma2(cur[r][2], xp, wB.x);
                ffma2(cur[r][3], xp, wB.y);
                ffma2(cur[r][4], xp, wC);
            }
        }

        // ---- sparse recurrent gathers (prev-step lists, lean loop) ----
#pragma unroll
        for (int r = 0; r < ROWS_PER_WARP; r++) {
            const unsigned short* lr = lst[r];
            const int cn = cnt[r];
            int i = 0;
            for (; i + 2 <= cn; i += 2) {
                gather1(g_WhT + (int)lr[i] * NPAD, L, cur[r]);
                gather1(g_WhT + (int)lr[i + 1] * NPAD, L, cur[r]);
            }
            if (i < cn) gather1(g_WhT + (int)lr[i] * NPAD, L, cur[r]);
        }
        __syncwarp();

        // ---- LIF 1 + rebuild spike lists ----
#pragma unroll
        for (int r = 0; r < ROWS_PER_WARP; r++) {
            int nc = 0;
#pragma unroll
            for (int p = 0; p < 5; p++) {
                unsigned long long d = fsub2(cur[r][p], v1[r][p]);
                unsigned long long vn = v1[r][p];
                ffma2(vn, d, HALF2);          // v + (cur - v)*0.5
                float lo, hi;
                upk2(vn, lo, hi);
                bool s0 = (lo >= 1.0f), s1 = (hi >= 1.0f);
                v1[r][p] = pk2(s0 ? 0.0f : lo, s1 ? 0.0f : hi);
                int nb = neuron_of(p, 0, L);
                unsigned m0 = __ballot_sync(0xffffffffu, s0);
                if (s0) lst[r][nc + __popc(m0 & lt_mask)] = (unsigned short)nb;
                nc += __popc(m0);
                unsigned m1 = __ballot_sync(0xffffffffu, s1);
                if (s1) lst[r][nc + __popc(m1 & lt_mask)] = (unsigned short)(nb + 1);
                nc += __popc(m1);
            }
            cnt[r] = nc;
        }
        __syncwarp();

        // ---- layer 2: bias + gather W2^T with new lists ----
        {
            ulonglong2 bA = *(const ulonglong2*)(b2s + 4 * L);
            ulonglong2 bB = *(const ulonglong2*)(b2s + 128 + 4 * L);
            unsigned long long bC = *(const unsigned long long*)(b2s + 256 + 2 * L);
#pragma unroll
            for (int r = 0; r < ROWS_PER_WARP; r++) {
                cur[r][0] = bA.x; cur[r][1] = bA.y;
                cur[r][2] = bB.x; cur[r][3] = bB.y;
                cur[r][4] = bC;
            }
        }
#pragma unroll
        for (int r = 0; r < ROWS_PER_WARP; r++) {
            const unsigned short* lr = lst[r];
            const int cn = cnt[r];
            int i = 0;
            for (; i + 2 <= cn; i += 2) {
                gather1(g_W2T + (int)lr[i] * NPAD, L, cur[r]);
                gather1(g_W2T + (int)lr[i + 1] * NPAD, L, cur[r]);
            }
            if (i < cn) gather1(g_W2T + (int)lr[i] * NPAD, L, cur[r]);
        }

        // ---- LIF 2: packed update + 8-bit spike counters ----
#pragma unroll
        for (int r = 0; r < ROWS_PER_WARP; r++) {
#pragma unroll
            for (int p = 0; p < 5; p++) {
                unsigned long long d = fsub2(cur[r][p], v2[r][p]);
                unsigned long long vn = v2[r][p];
                ffma2(vn, d, HALF2);
                float lo, hi;
                upk2(vn, lo, hi);
                bool s0 = (lo >= 1.0f), s1 = (hi >= 1.0f);
                v2[r][p] = pk2(s0 ? 0.0f : lo, s1 ? 0.0f : hi);
                int s_lo = 2 * p, s_hi = 2 * p + 1;
                c2[r][s_lo >> 2] += s0 ? (1u << (8 * (s_lo & 3))) : 0u;
                c2[r][s_hi >> 2] += s1 ? (1u << (8 * (s_hi & 3))) : 0u;
            }
        }
    }

    // ---- epilogue: out[row] = counts @ W3^T + 101*b3 ----
#pragma unroll
    for (int r = 0; r < ROWS_PER_WARP; r++) {
        float acc[OUT_DIM];
#pragma unroll
        for (int o = 0; o < OUT_DIM; o++) acc[o] = 0.0f;
#pragma unroll
        for (int s = 0; s < 10; s++) {
            int p = s >> 1, e = s & 1;
            int n = neuron_of(p, e, L);
            float c = (float)((c2[r][s >> 2] >> (8 * (s & 3))) & 255u);
            if (n < HID && c != 0.0f) {
#pragma unroll
                for (int o = 0; o < OUT_DIM; o++)
                    acc[o] = fmaf(c, W3[o * HID + n], acc[o]);
            }
        }
#pragma unroll
        for (int o = 0; o < OUT_DIM; o++) {
            float sv = acc[o];
            sv += __shfl_xor_sync(0xffffffffu, sv, 16);
            sv += __shfl_xor_sync(0xffffffffu, sv, 8);
            sv += __shfl_xor_sync(0xffffffffu, sv, 4);
            sv += __shfl_xor_sync(0xffffffffu, sv, 2);
            sv += __shfl_xor_sync(0xffffffffu, sv, 1);
            if (L == 0) out[(row0 + r) * OUT_DIM + o] = sv + 101.0f * b3[o];
        }
    }
}

extern "C" void kernel_launch(void* const* d_in, const int* in_sizes, int n_in,
                              void* d_out, int out_size) {
    const float* x  = (const float*)d_in[0];
    const float* W1 = (const float*)d_in[1];
    const float* b1 = (const float*)d_in[2];
    const float* bh = (const float*)d_in[4];
    const float* Wh = (const float*)d_in[3];
    const float* b2 = (const float*)d_in[6];
    const float* W2 = (const float*)d_in[5];
    const float* W3 = (const float*)d_in[7];
    const float* b3 = (const float*)d_in[8];
    float* out = (float*)d_out;

    {
        int total = HID * NPAD;
        int threads = 256;
        int blocks = (total + threads - 1) / threads;
        prep_kernel<<<blocks, threads>>>(Wh, W2);
    }

    size_t smem = (size_t)IN_DIM * NPAD * 4     // W1Ts
                + NPAD * 4                       // bsum
                + NPAD * 4                       // b2s
                + (size_t)ROWS_PER_BLK * AL_STRIDE * 2;
    cudaFuncSetAttribute(snn_kernel, cudaFuncAttributeMaxDynamicSharedMemorySize,
                         (int)smem);
    snn_kernel<<<NUM_BLKS, THREADS_PER_BLK, smem>>>(x, W1, b1, bh, b2, W3, b3, out);
}